// round 4
// baseline (speedup 1.0000x reference)
#include <cuda_runtime.h>

#define BB 4
#define LL 1024
#define DD 512
#define HH 8
#define HD 64

// 128 MB scratch: S scores, overwritten in-place by normalized P.
__device__ float g_S[(size_t)BB * HH * LL * LL];
__device__ float g_wacc[BB * LL];

// ---------------------------------------------------------------------------
__global__ void zero_wacc_kernel() {
    int i = blockIdx.x * blockDim.x + threadIdx.x;
    if (i < BB * LL) g_wacc[i] = 0.f;
}

// ---------------------------------------------------------------------------
// GEMM1: S[bh][l][m] = sum_k K[b,l,h*64+k] * Q[b,m,h*64+k]
// CTA tile 128x128, kc=32 (two chunks of the K=64 reduction), 256 thr, 8x8 micro
__global__ __launch_bounds__(256) void gemm1_kernel(
    const float* __restrict__ Kp, const float* __restrict__ Qp,
    const float* __restrict__ doc)
{
    __shared__ float As[32 * 132];   // [k][row], pad stride 132
    __shared__ float Bs[32 * 132];
    int bh = blockIdx.z;
    int b = bh >> 3, h = bh & 7;
    int len = (int)doc[b];
    int l0 = blockIdx.y * 128, m0 = blockIdx.x * 128;
    if (l0 >= len || m0 >= len) return;   // tile never consumed downstream

    const float* Kb = Kp + (size_t)b * LL * DD + h * HD;
    const float* Qb = Qp + (size_t)b * LL * DD + h * HD;
    int tid = threadIdx.x;
    int tx = tid & 15, ty = tid >> 4;

    float acc[8][8];
#pragma unroll
    for (int i = 0; i < 8; i++)
#pragma unroll
        for (int j = 0; j < 8; j++) acc[i][j] = 0.f;

    for (int kc = 0; kc < 64; kc += 32) {
#pragma unroll
        for (int i = 0; i < 16; ++i) {
            int idx = tid + i * 256;           // 0..8191
            int row = idx >> 5, k = idx & 31;  // lanes: consecutive k, same row -> coalesced LDG
            As[k * 132 + row] = Kb[(size_t)(l0 + row) * DD + kc + k];
            Bs[k * 132 + row] = Qb[(size_t)(m0 + row) * DD + kc + k];
        }
        __syncthreads();
#pragma unroll
        for (int k = 0; k < 32; ++k) {
            float4 a0 = *(const float4*)&As[k * 132 + ty * 8];
            float4 a1 = *(const float4*)&As[k * 132 + ty * 8 + 4];
            float4 b0 = *(const float4*)&Bs[k * 132 + tx * 8];
            float4 b1 = *(const float4*)&Bs[k * 132 + tx * 8 + 4];
            float a[8]  = {a0.x, a0.y, a0.z, a0.w, a1.x, a1.y, a1.z, a1.w};
            float bb[8] = {b0.x, b0.y, b0.z, b0.w, b1.x, b1.y, b1.z, b1.w};
#pragma unroll
            for (int i = 0; i < 8; i++)
#pragma unroll
                for (int j = 0; j < 8; j++) acc[i][j] += a[i] * bb[j];
        }
        __syncthreads();
    }

    float* Sp = g_S + ((size_t)bh * LL + l0) * LL + m0;
#pragma unroll
    for (int i = 0; i < 8; i++) {
        int row = ty * 8 + i;
        *(float4*)&Sp[(size_t)row * LL + tx * 8] =
            make_float4(acc[i][0], acc[i][1], acc[i][2], acc[i][3]);
        *(float4*)&Sp[(size_t)row * LL + tx * 8 + 4] =
            make_float4(acc[i][4], acc[i][5], acc[i][6], acc[i][7]);
    }
}

// ---------------------------------------------------------------------------
// LN over heads + masked softmax over m + column-sum accumulation for w.
// One CTA per (b,l). Writes P in place over S.
__global__ __launch_bounds__(256) void lnsm_kernel(
    const float* __restrict__ doc, const float* __restrict__ gamma,
    const float* __restrict__ beta)
{
    __shared__ float s[HH][LL];   // 32 KB
    int b = blockIdx.y, l = blockIdx.x;
    int len = (int)doc[b];
    int tid = threadIdx.x;

    if (l >= len) {   // fully masked row -> P = 0 everywhere (softmax NaN->0)
        for (int h = 0; h < HH; ++h) {
            float* P = g_S + ((size_t)(b * HH + h) * LL + l) * LL;
            for (int m = tid; m < LL; m += 256) P[m] = 0.f;
        }
        return;
    }

    for (int h = 0; h < HH; ++h) {
        const float* Sr = g_S + ((size_t)(b * HH + h) * LL + l) * LL;
        for (int m = tid; m < len; m += 256) s[h][m] = Sr[m];
    }
    __syncthreads();

    float ga[HH], be[HH];
#pragma unroll
    for (int h = 0; h < HH; h++) { ga[h] = gamma[h]; be[h] = beta[h]; }

    // LayerNorm across heads at each (l,m)
    for (int m = tid; m < len; m += 256) {
        float x[HH]; float mu = 0.f;
#pragma unroll
        for (int h = 0; h < HH; h++) { x[h] = s[h][m]; mu += x[h]; }
        mu *= (1.f / HH);
        float var = 0.f;
#pragma unroll
        for (int h = 0; h < HH; h++) { float d0 = x[h] - mu; var += d0 * d0; }
        var *= (1.f / HH);
        float rstd = rsqrtf(var + 1e-5f);
#pragma unroll
        for (int h = 0; h < HH; h++) s[h][m] = (x[h] - mu) * rstd * ga[h] + be[h];
    }
    __syncthreads();

    // per-head masked softmax: warp w handles head w (8 warps == 8 heads)
    int w = tid >> 5, lane = tid & 31;
    {
        float mx = -1e30f;
        for (int m = lane; m < len; m += 32) mx = fmaxf(mx, s[w][m]);
#pragma unroll
        for (int o = 16; o; o >>= 1) mx = fmaxf(mx, __shfl_xor_sync(0xffffffffu, mx, o));
        float sum = 0.f;
        for (int m = lane; m < len; m += 32) {
            float e = __expf(s[w][m] - mx);
            s[w][m] = e; sum += e;
        }
#pragma unroll
        for (int o = 16; o; o >>= 1) sum += __shfl_xor_sync(0xffffffffu, sum, o);
        float inv = 1.f / sum;
        for (int m = lane; m < len; m += 32) s[w][m] *= inv;
    }
    __syncthreads();

    // write P (zeros beyond len) and accumulate column sums for w
    for (int h = 0; h < HH; ++h) {
        float* P = g_S + ((size_t)(b * HH + h) * LL + l) * LL;
        for (int m = tid; m < LL; m += 256) P[m] = (m < len) ? s[h][m] : 0.f;
    }
    for (int m = tid; m < len; m += 256) {
        float c = 0.f;
#pragma unroll
        for (int h = 0; h < HH; h++) c += s[h][m];
        atomicAdd(&g_wacc[b * LL + m], c);
    }
}

// ---------------------------------------------------------------------------
// Finalize w: scale by 1/(H*len), masked softmax over m, write [B,L].
__global__ __launch_bounds__(256) void wfin_kernel(
    const float* __restrict__ doc, float* __restrict__ wout)
{
    __shared__ float red[8];
    __shared__ float s_max, s_inv;
    int b = blockIdx.x;
    int len = (int)doc[b];
    int tid = threadIdx.x, w = tid >> 5, lane = tid & 31;
    float scale = 1.f / (8.f * (float)len);

    float mx = -1e30f;
    for (int m = tid; m < len; m += 256) mx = fmaxf(mx, g_wacc[b * LL + m]);
#pragma unroll
    for (int o = 16; o; o >>= 1) mx = fmaxf(mx, __shfl_xor_sync(0xffffffffu, mx, o));
    if (lane == 0) red[w] = mx;
    __syncthreads();
    if (tid == 0) {
        float v = red[0];
        for (int i = 1; i < 8; i++) v = fmaxf(v, red[i]);
        s_max = v * scale;   // scale > 0: max(scale*x) = scale*max(x)
    }
    __syncthreads();
    float bmax = s_max;

    float sum = 0.f;
    for (int m = tid; m < len; m += 256)
        sum += __expf(g_wacc[b * LL + m] * scale - bmax);
#pragma unroll
    for (int o = 16; o; o >>= 1) sum += __shfl_xor_sync(0xffffffffu, sum, o);
    if (lane == 0) red[w] = sum;
    __syncthreads();
    if (tid == 0) {
        float v = 0.f;
        for (int i = 0; i < 8; i++) v += red[i];
        s_inv = 1.f / v;
    }
    __syncthreads();
    float inv = s_inv;

    for (int m = tid; m < LL; m += 256)
        wout[b * LL + m] = (m < len)
            ? __expf(g_wacc[b * LL + m] * scale - bmax) * inv : 0.f;
}

// ---------------------------------------------------------------------------
// GEMM2: out[b,l,h*64+d] = sum_m P[bh][l][m] * V[b,m,h*64+d]
// CTA tile 64(M=l) x 64(N=d), kc=32, 128 thr, 8x4 micro. k-loop stops at len.
__global__ __launch_bounds__(128) void gemm2_kernel(
    const float* __restrict__ Vp, const float* __restrict__ doc,
    float* __restrict__ outp)
{
    __shared__ float Ps[32 * 68];   // [k(m)][row(l)]
    __shared__ float Vs[32 * 68];   // [k(m)][col(d)]
    int b = blockIdx.z, h = blockIdx.y;
    int len = (int)doc[b];
    int l0 = blockIdx.x * 64;
    int tid = threadIdx.x;
    int tx = tid & 15, ty = tid >> 4;

    float* outb = outp + ((size_t)b * LL + l0) * DD + h * HD;
    if (l0 >= len) {   // fully masked rows -> out tile = 0 (d_out is poisoned)
        for (int i = ty; i < 64; i += 8)
            *(float4*)&outb[(size_t)i * DD + tx * 4] = make_float4(0, 0, 0, 0);
        return;
    }

    const float* Pb = g_S + ((size_t)(b * HH + h) * LL + l0) * LL;
    const float* Vb = Vp + (size_t)b * LL * DD + h * HD;

    float acc[8][4];
#pragma unroll
    for (int i = 0; i < 8; i++)
#pragma unroll
        for (int j = 0; j < 4; j++) acc[i][j] = 0.f;

    int kend = (len + 31) & ~31;   // P columns in [len, kend) are zero
    for (int mc = 0; mc < kend; mc += 32) {
#pragma unroll
        for (int i = 0; i < 16; ++i) {
            int idx = tid + i * 128;
            int row = idx >> 5, k = idx & 31;   // coalesced over k
            Ps[k * 68 + row] = Pb[(size_t)row * LL + mc + k];
        }
#pragma unroll
        for (int i = 0; i < 16; ++i) {
            int idx = tid + i * 128;
            int k = idx >> 6, col = idx & 63;   // coalesced over col
            Vs[k * 68 + col] = Vb[(size_t)(mc + k) * DD + col];
        }
        __syncthreads();
#pragma unroll
        for (int k = 0; k < 32; ++k) {
            float4 a0 = *(const float4*)&Ps[k * 68 + ty * 8];
            float4 a1 = *(const float4*)&Ps[k * 68 + ty * 8 + 4];
            float4 b0 = *(const float4*)&Vs[k * 68 + tx * 4];
            float a[8]  = {a0.x, a0.y, a0.z, a0.w, a1.x, a1.y, a1.z, a1.w};
            float bb[4] = {b0.x, b0.y, b0.z, b0.w};
#pragma unroll
            for (int i = 0; i < 8; i++)
#pragma unroll
                for (int j = 0; j < 4; j++) acc[i][j] += a[i] * bb[j];
        }
        __syncthreads();
    }

#pragma unroll
    for (int i = 0; i < 8; i++) {
        int row = ty * 8 + i;
        *(float4*)&outb[(size_t)row * DD + tx * 4] =
            make_float4(acc[i][0], acc[i][1], acc[i][2], acc[i][3]);
    }
}

// ---------------------------------------------------------------------------
extern "C" void kernel_launch(void* const* d_in, const int* in_sizes, int n_in,
                              void* d_out, int out_size) {
    const float* K     = (const float*)d_in[0];
    const float* Q     = (const float*)d_in[1];
    const float* V     = (const float*)d_in[2];
    const float* doc   = (const float*)d_in[3];
    const float* gamma = (const float*)d_in[4];
    const float* beta  = (const float*)d_in[5];
    // d_in[6] pad_mask, d_in[7] bx_packed: fully derivable from doc_sizes; unused.

    float* outp = (float*)d_out;

    zero_wacc_kernel<<<16, 256>>>();

    dim3 g1(LL / 128, LL / 128, BB * HH);   // (8, 8, 32)
    gemm1_kernel<<<g1, 256>>>(K, Q, doc);

    dim3 g2(LL, BB);                         // one CTA per (b, l)
    lnsm_kernel<<<g2, 256>>>(doc, gamma, beta);

    if (out_size >= BB * LL * DD + BB * LL) {
        float* wout = outp + (size_t)BB * LL * DD;
        wfin_kernel<<<BB, 256>>>(doc, wout);
    }

    dim3 g3(LL / 64, HH, BB);                // (16, 8, 4)
    gemm2_kernel<<<g3, 128>>>(V, doc, outp);
}

// round 6
// speedup vs baseline: 1.4801x; 1.4801x over previous
#include <cuda_runtime.h>
#include <cuda_bf16.h>
#include <cstdint>

#define BB 4
#define LL 1024
#define DD 512
#define HH 8
#define HD 64

// ---------------------------------------------------------------------------
// Device scratch (static: no allocations allowed)
__device__ __align__(256) float g_S[(size_t)BB * HH * LL * LL];           // 128 MB scores
__device__ __align__(256) __nv_bfloat16 g_Phi[(size_t)BB * HH * LL * LL]; // 64 MB
__device__ __align__(256) __nv_bfloat16 g_Plo[(size_t)BB * HH * LL * LL]; // 64 MB
__device__ __align__(256) __nv_bfloat16 g_Khi[(size_t)BB * HH * LL * HD];
__device__ __align__(256) __nv_bfloat16 g_Klo[(size_t)BB * HH * LL * HD];
__device__ __align__(256) __nv_bfloat16 g_Qhi[(size_t)BB * HH * LL * HD];
__device__ __align__(256) __nv_bfloat16 g_Qlo[(size_t)BB * HH * LL * HD];
__device__ __align__(256) __nv_bfloat16 g_Vthi[(size_t)BB * HH * HD * LL]; // [bh][d][m]
__device__ __align__(256) __nv_bfloat16 g_Vtlo[(size_t)BB * HH * HD * LL];
__device__ float g_wacc[BB * LL];

// ---------------------------------------------------------------------------
__device__ __forceinline__ uint32_t smem_u32(const void* p) {
    uint32_t a;
    asm("{ .reg .u64 t; cvta.to.shared.u64 t, %1; cvt.u32.u64 %0, t; }" : "=r"(a) : "l"(p));
    return a;
}
__device__ __forceinline__ void ldm_x4(uint32_t& r0, uint32_t& r1, uint32_t& r2,
                                       uint32_t& r3, uint32_t addr) {
    asm volatile("ldmatrix.sync.aligned.m8n8.x4.shared.b16 {%0,%1,%2,%3}, [%4];"
                 : "=r"(r0), "=r"(r1), "=r"(r2), "=r"(r3) : "r"(addr));
}
__device__ __forceinline__ void mma_bf16(float& c0, float& c1, float& c2, float& c3,
                                         uint32_t a0, uint32_t a1, uint32_t a2, uint32_t a3,
                                         uint32_t b0, uint32_t b1) {
    asm volatile("mma.sync.aligned.m16n8k16.row.col.f32.bf16.bf16.f32 "
                 "{%0,%1,%2,%3}, {%4,%5,%6,%7}, {%8,%9}, {%0,%1,%2,%3};"
                 : "+f"(c0), "+f"(c1), "+f"(c2), "+f"(c3)
                 : "r"(a0), "r"(a1), "r"(a2), "r"(a3), "r"(b0), "r"(b1));
}

// smem row stride for MMA tiles: 40 bf16 = 80 B; 80*r mod 128 hits all eight
// 16B banks across r=0..7 -> conflict-free ldmatrix.
#define SSTR 40

// ---------------------------------------------------------------------------
// Prep 1: split K,Q fp32 -> bf16 hi/lo in [bh][l][64] layout; zero wacc.
__global__ __launch_bounds__(256) void prep_kq_kernel(
    const float* __restrict__ Kp, const float* __restrict__ Qp)
{
    int idx = blockIdx.x * 256 + threadIdx.x;
    int k = idx & 63, h = (idx >> 6) & 7, l = (idx >> 9) & 1023, b = idx >> 19;
    size_t o = (((size_t)(b * 8 + h) * 1024 + l) << 6) | (unsigned)k;
    float kv = Kp[idx];
    __nv_bfloat16 khi = __float2bfloat16(kv);
    g_Khi[o] = khi;
    g_Klo[o] = __float2bfloat16(kv - __bfloat162float(khi));
    float qv = Qp[idx];
    __nv_bfloat16 qhi = __float2bfloat16(qv);
    g_Qhi[o] = qhi;
    g_Qlo[o] = __float2bfloat16(qv - __bfloat162float(qhi));
    if (idx < BB * LL) g_wacc[idx] = 0.f;
}

// Prep 2: transpose-split V [b][m][h*64+d] -> Vt hi/lo [bh][d][m]
__global__ __launch_bounds__(256) void prep_v_kernel(const float* __restrict__ Vp)
{
    __shared__ float t[32][33];
    int b = blockIdx.z;
    int m0 = blockIdx.x * 32, hd0 = blockIdx.y * 32;
    int tx = threadIdx.x, ty = threadIdx.y;   // (32, 8)
#pragma unroll
    for (int i = 0; i < 4; i++)
        t[ty + 8 * i][tx] = Vp[((size_t)b * 1024 + m0 + ty + 8 * i) * 512 + hd0 + tx];
    __syncthreads();
#pragma unroll
    for (int i = 0; i < 4; i++) {
        int hd = hd0 + ty + 8 * i;
        int h = hd >> 6, d = hd & 63;
        float x = t[tx][ty + 8 * i];
        __nv_bfloat16 hi = __float2bfloat16(x);
        size_t o = ((size_t)(b * 8 + h) * 64 + d) * 1024 + m0 + tx;
        g_Vthi[o] = hi;
        g_Vtlo[o] = __float2bfloat16(x - __bfloat162float(hi));
    }
}

// ---------------------------------------------------------------------------
// GEMM1 (mma.sync bf16): S[bh][l][m] = K[l,:]·Q[m,:], tile 128x128, K=64.
// 8 warps: warp tile 64(M) x 32(N). Split precision Ah·Bh + Ah·Bl + Al·Bh.
__global__ __launch_bounds__(256) void gemm1_kernel(const float* __restrict__ doc)
{
    __shared__ __nv_bfloat16 sA[2][128 * SSTR];   // hi, lo  (K-chunk = 32)
    __shared__ __nv_bfloat16 sB[2][128 * SSTR];

    int bh = blockIdx.z;
    int b = bh >> 3;
    int len = (int)doc[b];
    int l0 = blockIdx.y * 128, m0 = blockIdx.x * 128;
    if (l0 >= len || m0 >= len) return;

    int tid = threadIdx.x, wid = tid >> 5, lane = tid & 31;
    int wm = (wid >> 2) * 64, wn = (wid & 3) * 32;

    const uint4* srcA[2] = { (const uint4*)(g_Khi + ((size_t)bh * 1024 + l0) * 64),
                             (const uint4*)(g_Klo + ((size_t)bh * 1024 + l0) * 64) };
    const uint4* srcB[2] = { (const uint4*)(g_Qhi + ((size_t)bh * 1024 + m0) * 64),
                             (const uint4*)(g_Qlo + ((size_t)bh * 1024 + m0) * 64) };

    float c[4][4][4];
#pragma unroll
    for (int i = 0; i < 4; i++)
#pragma unroll
        for (int j = 0; j < 4; j++)
#pragma unroll
            for (int q = 0; q < 4; q++) c[i][j][q] = 0.f;

    // lane-dependent ldmatrix base offsets (bytes)
    uint32_t aoff = (uint32_t)(wm + (lane & 15)) * (SSTR * 2) + (((uint32_t)lane >> 4) << 4);
    uint32_t boff = (uint32_t)(wn + (lane & 7) + (((uint32_t)lane >> 4) << 3)) * (SSTR * 2)
                  + ((((uint32_t)lane >> 3) & 1) << 4);
    uint32_t sAh = smem_u32(&sA[0][0]), sAl = smem_u32(&sA[1][0]);
    uint32_t sBh = smem_u32(&sB[0][0]), sBl = smem_u32(&sB[1][0]);

    for (int kc = 0; kc < 64; kc += 32) {
        if (kc) __syncthreads();
        // stage 32-wide K chunk: each array 128 rows x 4 uint4
#pragma unroll
        for (int e = 0; e < 2; e++) {
#pragma unroll
            for (int i = 0; i < 2; i++) {
                int idx = tid + i * 256;
                int row = idx >> 2, c4 = idx & 3;
                *(uint4*)((char*)&sA[e][0] + row * (SSTR * 2) + c4 * 16) =
                    srcA[e][(size_t)row * 8 + (kc >> 3) + c4];
                *(uint4*)((char*)&sB[e][0] + row * (SSTR * 2) + c4 * 16) =
                    srcB[e][(size_t)row * 8 + (kc >> 3) + c4];
            }
        }
        __syncthreads();

#pragma unroll
        for (int ks = 0; ks < 2; ks++) {
            uint32_t k0b = ks * 32;   // 16 bf16 = 32 bytes
            uint32_t Ah[4][4], Al[4][4], Bh[2][4], Bl[2][4];
#pragma unroll
            for (int mt = 0; mt < 4; mt++) {
                ldm_x4(Ah[mt][0], Ah[mt][1], Ah[mt][2], Ah[mt][3],
                       sAh + aoff + mt * 16 * (SSTR * 2) + k0b);
                ldm_x4(Al[mt][0], Al[mt][1], Al[mt][2], Al[mt][3],
                       sAl + aoff + mt * 16 * (SSTR * 2) + k0b);
            }
#pragma unroll
            for (int nt = 0; nt < 2; nt++) {
                ldm_x4(Bh[nt][0], Bh[nt][1], Bh[nt][2], Bh[nt][3],
                       sBh + boff + nt * 16 * (SSTR * 2) + k0b);
                ldm_x4(Bl[nt][0], Bl[nt][1], Bl[nt][2], Bl[nt][3],
                       sBl + boff + nt * 16 * (SSTR * 2) + k0b);
            }
#pragma unroll
            for (int mt = 0; mt < 4; mt++)
#pragma unroll
                for (int ns = 0; ns < 4; ns++) {
                    float* cc = c[mt][ns];
                    uint32_t* bh_ = &Bh[ns >> 1][(ns & 1) * 2];
                    uint32_t* bl_ = &Bl[ns >> 1][(ns & 1) * 2];
                    mma_bf16(cc[0], cc[1], cc[2], cc[3],
                             Ah[mt][0], Ah[mt][1], Ah[mt][2], Ah[mt][3], bh_[0], bh_[1]);
                    mma_bf16(cc[0], cc[1], cc[2], cc[3],
                             Ah[mt][0], Ah[mt][1], Ah[mt][2], Ah[mt][3], bl_[0], bl_[1]);
                    mma_bf16(cc[0], cc[1], cc[2], cc[3],
                             Al[mt][0], Al[mt][1], Al[mt][2], Al[mt][3], bh_[0], bh_[1]);
                }
        }
    }

    // epilogue: c fragment (m = t/4 [+8], n = (t%4)*2)
    float* Sp = g_S + ((size_t)bh * 1024 + l0) * 1024 + m0;
#pragma unroll
    for (int mt = 0; mt < 4; mt++) {
        int r0 = wm + mt * 16 + (lane >> 2);
#pragma unroll
        for (int ns = 0; ns < 4; ns++) {
            int n = wn + ns * 8 + (lane & 3) * 2;
            *(float2*)&Sp[(size_t)r0 * 1024 + n] = make_float2(c[mt][ns][0], c[mt][ns][1]);
            *(float2*)&Sp[(size_t)(r0 + 8) * 1024 + n] = make_float2(c[mt][ns][2], c[mt][ns][3]);
        }
    }
}

// ---------------------------------------------------------------------------
// LN over heads + masked softmax; emits P as bf16 hi/lo; accumulates col sums.
__global__ __launch_bounds__(256) void lnsm_kernel(
    const float* __restrict__ doc, const float* __restrict__ gamma,
    const float* __restrict__ beta)
{
    __shared__ float s[HH][LL];
    int b = blockIdx.y, l = blockIdx.x;
    int len = (int)doc[b];
    int kend  = (len + 63) & ~63;
    int lceil = (len + 127) & ~127;
    int tid = threadIdx.x;

    if (l >= len) {
        if (l >= lceil) return;
        for (int h = 0; h < HH; ++h) {
            size_t o = ((size_t)(b * HH + h) * LL + l) * LL;
            for (int m = tid; m < kend; m += 256) {
                g_Phi[o + m] = __float2bfloat16(0.f);
                g_Plo[o + m] = __float2bfloat16(0.f);
            }
        }
        return;
    }

    for (int h = 0; h < HH; ++h) {
        const float* Sr = g_S + ((size_t)(b * HH + h) * LL + l) * LL;
        for (int m = tid; m < len; m += 256) s[h][m] = Sr[m];
    }
    __syncthreads();

    float ga[HH], be[HH];
#pragma unroll
    for (int h = 0; h < HH; h++) { ga[h] = gamma[h]; be[h] = beta[h]; }

    for (int m = tid; m < len; m += 256) {
        float x[HH]; float mu = 0.f;
#pragma unroll
        for (int h = 0; h < HH; h++) { x[h] = s[h][m]; mu += x[h]; }
        mu *= (1.f / HH);
        float var = 0.f;
#pragma unroll
        for (int h = 0; h < HH; h++) { float d0 = x[h] - mu; var += d0 * d0; }
        var *= (1.f / HH);
        float rstd = rsqrtf(var + 1e-5f);
#pragma unroll
        for (int h = 0; h < HH; h++) s[h][m] = (x[h] - mu) * rstd * ga[h] + be[h];
    }
    __syncthreads();

    int w = tid >> 5, lane = tid & 31;
    {
        float mx = -1e30f;
        for (int m = lane; m < len; m += 32) mx = fmaxf(mx, s[w][m]);
#pragma unroll
        for (int o = 16; o; o >>= 1) mx = fmaxf(mx, __shfl_xor_sync(0xffffffffu, mx, o));
        float sum = 0.f;
        for (int m = lane; m < len; m += 32) {
            float e = __expf(s[w][m] - mx);
            s[w][m] = e; sum += e;
        }
#pragma unroll
        for (int o = 16; o; o >>= 1) sum += __shfl_xor_sync(0xffffffffu, sum, o);
        float inv = 1.f / sum;
        for (int m = lane; m < len; m += 32) s[w][m] *= inv;
    }
    __syncthreads();

    for (int h = 0; h < HH; ++h) {
        size_t o = ((size_t)(b * HH + h) * LL + l) * LL;
        for (int m = tid; m < kend; m += 256) {
            float p = (m < len) ? s[h][m] : 0.f;
            __nv_bfloat16 hi = __float2bfloat16(p);
            g_Phi[o + m] = hi;
            g_Plo[o + m] = __float2bfloat16(p - __bfloat162float(hi));
        }
    }
    for (int m = tid; m < len; m += 256) {
        float cacc = 0.f;
#pragma unroll
        for (int h = 0; h < HH; h++) cacc += s[h][m];
        atomicAdd(&g_wacc[b * LL + m], cacc);
    }
}

// ---------------------------------------------------------------------------
// Finalize w: one 1024-thread block per batch, single pass.
__global__ __launch_bounds__(1024) void wfin_kernel(
    const float* __restrict__ doc, float* __restrict__ wout)
{
    __shared__ float red[32];
    __shared__ float s_bmax, s_inv;
    int b = blockIdx.x;
    int len = (int)doc[b];
    int tid = threadIdx.x, w = tid >> 5, lane = tid & 31;
    float scale = 1.f / (8.f * (float)len);

    float v = (tid < len) ? g_wacc[b * LL + tid] * scale : -1e30f;
    float mx = v;
#pragma unroll
    for (int o = 16; o; o >>= 1) mx = fmaxf(mx, __shfl_xor_sync(0xffffffffu, mx, o));
    if (lane == 0) red[w] = mx;
    __syncthreads();
    if (w == 0) {
        float t = red[lane];
#pragma unroll
        for (int o = 16; o; o >>= 1) t = fmaxf(t, __shfl_xor_sync(0xffffffffu, t, o));
        if (lane == 0) s_bmax = t;
    }
    __syncthreads();
    float e = (tid < len) ? __expf(v - s_bmax) : 0.f;
    float sum = e;
#pragma unroll
    for (int o = 16; o; o >>= 1) sum += __shfl_xor_sync(0xffffffffu, sum, o);
    if (lane == 0) red[w] = sum;
    __syncthreads();
    if (w == 0) {
        float t = red[lane];
#pragma unroll
        for (int o = 16; o; o >>= 1) t += __shfl_xor_sync(0xffffffffu, t, o);
        if (lane == 0) s_inv = 1.f / t;
    }
    __syncthreads();
    wout[b * LL + tid] = e * s_inv;
}

// ---------------------------------------------------------------------------
// GEMM2 (mma.sync bf16): out[l,d] = sum_m P[l,m]·Vt[d,m]; tile 128(l) x 64(d),
// K chunked by 32 up to kend. 8 warps: warp tile 32(M) x 32(N).
__global__ __launch_bounds__(256) void gemm2_kernel(
    const float* __restrict__ doc, float* __restrict__ outp)
{
    __shared__ __nv_bfloat16 sP[2][128 * SSTR];
    __shared__ __nv_bfloat16 sV[2][64 * SSTR];

    int b = blockIdx.z, h = blockIdx.y;
    int bh = b * 8 + h;
    int len = (int)doc[b];
    int l0 = blockIdx.x * 128;
    int tid = threadIdx.x, wid = tid >> 5, lane = tid & 31;

    if (l0 >= len) {   // output rows are zero (d_out is poisoned)
        float* dst = outp + ((size_t)b * 1024 + l0 + (tid >> 1)) * 512 + h * 64;
        float4 z = make_float4(0, 0, 0, 0);
#pragma unroll
        for (int j = 0; j < 8; j++) ((float4*)dst)[(tid & 1) * 8 + j] = z;
        return;
    }

    int wm = (wid >> 1) * 32, wn = (wid & 1) * 32;

    const uint4* srcP[2] = { (const uint4*)(g_Phi + ((size_t)bh * 1024 + l0) * 1024),
                             (const uint4*)(g_Plo + ((size_t)bh * 1024 + l0) * 1024) };
    const uint4* srcV[2] = { (const uint4*)(g_Vthi + (size_t)bh * 64 * 1024),
                             (const uint4*)(g_Vtlo + (size_t)bh * 64 * 1024) };

    float c[2][4][4];
#pragma unroll
    for (int i = 0; i < 2; i++)
#pragma unroll
        for (int j = 0; j < 4; j++)
#pragma unroll
            for (int q = 0; q < 4; q++) c[i][j][q] = 0.f;

    uint32_t aoff = (uint32_t)(wm + (lane & 15)) * (SSTR * 2) + (((uint32_t)lane >> 4) << 4);
    uint32_t boff = (uint32_t)(wn + (lane & 7) + (((uint32_t)lane >> 4) << 3)) * (SSTR * 2)
                  + ((((uint32_t)lane >> 3) & 1) << 4);
    uint32_t sPh = smem_u32(&sP[0][0]), sPl = smem_u32(&sP[1][0]);
    uint32_t sVh = smem_u32(&sV[0][0]), sVl = smem_u32(&sV[1][0]);

    int kend = (len + 31) & ~31;
    for (int mc = 0; mc < kend; mc += 32) {
        if (mc) __syncthreads();
        int mq = mc >> 3;   // uint4 offset
#pragma unroll
        for (int e = 0; e < 2; e++) {
#pragma unroll
            for (int i = 0; i < 2; i++) {
                int idx = tid + i * 256;
                int row = idx >> 2, c4 = idx & 3;
                *(uint4*)((char*)&sP[e][0] + row * (SSTR * 2) + c4 * 16) =
                    srcP[e][(size_t)row * 128 + mq + c4];
            }
            {
                int row = tid >> 2, c4 = tid & 3;
                *(uint4*)((char*)&sV[e][0] + row * (SSTR * 2) + c4 * 16) =
                    srcV[e][(size_t)row * 128 + mq + c4];
            }
        }
        __syncthreads();

#pragma unroll
        for (int ks = 0; ks < 2; ks++) {
            uint32_t k0b = ks * 32;
            uint32_t Ah[2][4], Al[2][4], Bh[2][4], Bl[2][4];
#pragma unroll
            for (int mt = 0; mt < 2; mt++) {
                ldm_x4(Ah[mt][0], Ah[mt][1], Ah[mt][2], Ah[mt][3],
                       sPh + aoff + mt * 16 * (SSTR * 2) + k0b);
                ldm_x4(Al[mt][0], Al[mt][1], Al[mt][2], Al[mt][3],
                       sPl + aoff + mt * 16 * (SSTR * 2) + k0b);
            }
#pragma unroll
            for (int nt = 0; nt < 2; nt++) {
                ldm_x4(Bh[nt][0], Bh[nt][1], Bh[nt][2], Bh[nt][3],
                       sVh + boff + nt * 16 * (SSTR * 2) + k0b);
                ldm_x4(Bl[nt][0], Bl[nt][1], Bl[nt][2], Bl[nt][3],
                       sVl + boff + nt * 16 * (SSTR * 2) + k0b);
            }
#pragma unroll
            for (int mt = 0; mt < 2; mt++)
#pragma unroll
                for (int ns = 0; ns < 4; ns++) {
                    float* cc = c[mt][ns];
                    uint32_t* bh_ = &Bh[ns >> 1][(ns & 1) * 2];
                    uint32_t* bl_ = &Bl[ns >> 1][(ns & 1) * 2];
                    mma_bf16(cc[0], cc[1], cc[2], cc[3],
                             Ah[mt][0], Ah[mt][1], Ah[mt][2], Ah[mt][3], bh_[0], bh_[1]);
                    mma_bf16(cc[0], cc[1], cc[2], cc[3],
                             Ah[mt][0], Ah[mt][1], Ah[mt][2], Ah[mt][3], bl_[0], bl_[1]);
                    mma_bf16(cc[0], cc[1], cc[2], cc[3],
                             Al[mt][0], Al[mt][1], Al[mt][2], Al[mt][3], bh_[0], bh_[1]);
                }
        }
    }

    float* dstb = outp + ((size_t)b * 1024 + l0) * 512 + h * 64;
#pragma unroll
    for (int mt = 0; mt < 2; mt++) {
        int r0 = wm + mt * 16 + (lane >> 2);
#pragma unroll
        for (int ns = 0; ns < 4; ns++) {
            int n = wn + ns * 8 + (lane & 3) * 2;
            *(float2*)&dstb[(size_t)r0 * 512 + n] = make_float2(c[mt][ns][0], c[mt][ns][1]);
            *(float2*)&dstb[(size_t)(r0 + 8) * 512 + n] = make_float2(c[mt][ns][2], c[mt][ns][3]);
        }
    }
}

// ---------------------------------------------------------------------------
extern "C" void kernel_launch(void* const* d_in, const int* in_sizes, int n_in,
                              void* d_out, int out_size) {
    const float* K     = (const float*)d_in[0];
    const float* Q     = (const float*)d_in[1];
    const float* V     = (const float*)d_in[2];
    const float* doc   = (const float*)d_in[3];
    const float* gamma = (const float*)d_in[4];
    const float* beta  = (const float*)d_in[5];
    // pad_mask / bx_packed derivable from doc_sizes; unused.

    float* outp = (float*)d_out;

    prep_kq_kernel<<<(BB * LL * DD) / 256, 256>>>(K, Q);
    prep_v_kernel<<<dim3(LL / 32, DD / 32, BB), dim3(32, 8)>>>(V);

    dim3 g1(LL / 128, LL / 128, BB * HH);      // (8, 8, 32)
    gemm1_kernel<<<g1, 256>>>(doc);

    dim3 g2(LL, BB);
    lnsm_kernel<<<g2, 256>>>(doc, gamma, beta);

    if (out_size >= BB * LL * DD + BB * LL) {
        float* wout = outp + (size_t)BB * LL * DD;
        wfin_kernel<<<BB, 1024>>>(doc, wout);
    }

    dim3 g3(LL / 128, HH, BB);                 // (8, 8, 4)
    gemm2_kernel<<<g3, 256>>>(doc, outp);
}